// round 1
// baseline (speedup 1.0000x reference)
#include <cuda_runtime.h>

#define BATCH 32
#define IMH 1024
#define IMW 1024
#define NBOX 96
#define ROWS_PER_BLOCK 8
#define NTHREADS 256

// Per-(batch, box) accumulated rectangle sums. Zeroed at the start of every
// kernel_launch by zero_kernel (device global scratch; no allocations).
__device__ float g_boxsum[BATCH * NBOX];

__global__ void zero_kernel() {
    int i = blockIdx.x * blockDim.x + threadIdx.x;
    if (i < BATCH * NBOX) g_boxsum[i] = 0.0f;
}

// One block = 8 consecutive rows of one batch image.
// Per row: load 1024 floats (float4/thread), block-wide exclusive scan into
// SMEM epref[0..1024], then threads 0..95 accumulate their box's
// (epref[x2]-epref[x1]) if the row is inside [y1, y2). One atomicAdd per
// (block, box) at the end.
__global__ __launch_bounds__(NTHREADS)
void row_scan_kernel(const float* __restrict__ img, const int* __restrict__ bb) {
    const int blocksPerBatch = IMH / ROWS_PER_BLOCK;
    const int b    = blockIdx.x / blocksPerBatch;
    const int row0 = (blockIdx.x % blocksPerBatch) * ROWS_PER_BLOCK;
    const int t    = threadIdx.x;
    const int lane = t & 31;
    const int warp = t >> 5;

    __shared__ float epref[IMW + 1];
    __shared__ float wsum[8];
    __shared__ int4  sbox[NBOX];

    if (t < NBOX) sbox[t] = ((const int4*)bb)[b * NBOX + t];
    __syncthreads();

    int x1 = 0, y1 = 0, x2 = 0, y2 = 0;
    bool valid = false;
    if (t < NBOX) {
        int4 box = sbox[t];
        x1 = min(max(box.x, 0), IMW);
        y1 = min(max(box.y, 0), IMW);
        x2 = min(max(box.z, 0), IMW);
        y2 = min(max(box.w, 0), IMW);
        valid = (x2 > x1) && (y2 > y1);
    }
    float acc = 0.0f;

    const float4* rowbase = (const float4*)(img + (size_t)b * IMH * IMW);

    for (int r = 0; r < ROWS_PER_BLOCK; ++r) {
        const int row = row0 + r;
        float4 v = rowbase[(size_t)row * (IMW / 4) + t];

        // thread-local inclusive prefixes over 4 elements
        float p0 = v.x;
        float p1 = p0 + v.y;
        float p2 = p1 + v.z;
        float p3 = p2 + v.w;

        // warp inclusive scan of per-thread sums (p3)
        float s = p3;
        #pragma unroll
        for (int o = 1; o < 32; o <<= 1) {
            float u = __shfl_up_sync(0xffffffffu, s, o);
            if (lane >= o) s += u;
        }
        if (lane == 31) wsum[warp] = s;
        __syncthreads();

        if (warp == 0) {
            float ws = (lane < 8) ? wsum[lane] : 0.0f;
            #pragma unroll
            for (int o = 1; o < 8; o <<= 1) {
                float u = __shfl_up_sync(0xffffffffu, ws, o);
                if (lane >= o) ws += u;
            }
            if (lane < 8) wsum[lane] = ws;   // inclusive warp-sums scan
        }
        __syncthreads();

        const float warpoff = (warp == 0) ? 0.0f : wsum[warp - 1];
        const float off = warpoff + (s - p3);     // exclusive offset of this thread

        epref[4 * t + 0] = off;
        epref[4 * t + 1] = off + p0;
        epref[4 * t + 2] = off + p1;
        epref[4 * t + 3] = off + p2;
        if (t == NTHREADS - 1) epref[IMW] = off + p3;
        __syncthreads();

        if (valid && y1 <= row && row < y2)
            acc += epref[x2] - epref[x1];
        __syncthreads();   // protect epref/wsum before next row overwrites
    }

    if (t < NBOX && valid && acc != 0.0f)
        atomicAdd(&g_boxsum[b * NBOX + t], acc);
}

// Final reduction: loss = sum over all boxes of relu(1 - box_sum),
// with invalid boxes forced to box_sum = 0 (matching the reference mask).
__global__ void loss_kernel(const int* __restrict__ bb, float* __restrict__ out) {
    const int t = threadIdx.x;
    float sum = 0.0f;
    for (int i = t; i < BATCH * NBOX; i += blockDim.x) {
        int4 box = ((const int4*)bb)[i];
        int x1 = min(max(box.x, 0), IMW);
        int y1 = min(max(box.y, 0), IMW);
        int x2 = min(max(box.z, 0), IMW);
        int y2 = min(max(box.w, 0), IMW);
        float s = ((x2 > x1) && (y2 > y1)) ? g_boxsum[i] : 0.0f;
        float v = 1.0f - s;
        sum += (v > 0.0f) ? v : 0.0f;
    }
    __shared__ float red[32];
    #pragma unroll
    for (int o = 16; o; o >>= 1) sum += __shfl_down_sync(0xffffffffu, sum, o);
    const int lane = t & 31, warp = t >> 5;
    if (lane == 0) red[warp] = sum;
    __syncthreads();
    if (warp == 0) {
        sum = (lane < (int)(blockDim.x >> 5)) ? red[lane] : 0.0f;
        #pragma unroll
        for (int o = 16; o; o >>= 1) sum += __shfl_down_sync(0xffffffffu, sum, o);
        if (lane == 0) *out = sum;
    }
}

extern "C" void kernel_launch(void* const* d_in, const int* in_sizes, int n_in,
                              void* d_out, int out_size) {
    const float* img = (const float*)d_in[0];   // (32,1,1024,1024) fp32
    const int*   bb  = (const int*)d_in[1];     // (32,96,4) int32
    float* out = (float*)d_out;

    zero_kernel<<<(BATCH * NBOX + 255) / 256, 256>>>();
    row_scan_kernel<<<BATCH * (IMH / ROWS_PER_BLOCK), NTHREADS>>>(img, bb);
    loss_kernel<<<1, 256>>>(bb, out);
}

// round 2
// speedup vs baseline: 1.0402x; 1.0402x over previous
#include <cuda_runtime.h>

#define BATCH 32
#define IMH 1024
#define IMW 1024
#define NBOX 96
#define WARPS 8
#define NTHREADS 256
#define ROWS_PER_WARP 2
#define ROWS_PER_BLOCK (WARPS * ROWS_PER_WARP)        // 16
#define GRID (BATCH * IMH / ROWS_PER_BLOCK)           // 2048
#define EP_STRIDE 1056                                // words; 16B-aligned stride, covers swizzle range

// Per-(batch,box) rectangle sums. Zero-initialized at module load; the last
// block of every launch resets it to zero after reading, so each graph replay
// starts from a clean state. No allocations anywhere.
__device__ float    g_boxsum[BATCH * NBOX];
__device__ unsigned g_done;

// SMEM bank swizzle: XOR bits [2:4] with bits [5:7] (16B-granule permute).
// Makes both access patterns conflict-free:
//   coalesced v4 at word 4*lane + 128*j, and chunk v4 at word 32*lane + 4*j.
// swz(1024) == 1024, so the row-total slot is stable.
__device__ __forceinline__ int swz(int idx) { return idx ^ (((idx >> 5) & 7) << 2); }

__global__ __launch_bounds__(NTHREADS)
void fused_kernel(const float* __restrict__ img, const int* __restrict__ bb,
                  float* __restrict__ out) {
    __shared__ __align__(16) float ep_s[WARPS * EP_STRIDE];

    const int t    = threadIdx.x;
    const int lane = t & 31;
    const int w    = t >> 5;
    const int blocksPerBatch = IMH / ROWS_PER_BLOCK;  // 64
    const int b       = blockIdx.x / blocksPerBatch;
    const int rowBase = (blockIdx.x % blocksPerBatch) * ROWS_PER_BLOCK + w * ROWS_PER_WARP;

    float* ep = ep_s + w * EP_STRIDE;

    // Each lane owns boxes lane, lane+32, lane+64 of its batch (read via L1/L2,
    // no block barrier needed).
    int   bx1[3], bx2[3], by1[3], by2[3];
    bool  bval[3];
    float bacc[3];
#pragma unroll
    for (int k = 0; k < 3; k++) {
        int4 box = __ldg(((const int4*)bb) + b * NBOX + lane + 32 * k);
        bx1[k] = min(max(box.x, 0), IMW);
        by1[k] = min(max(box.y, 0), IMW);
        bx2[k] = min(max(box.z, 0), IMW);
        by2[k] = min(max(box.w, 0), IMW);
        bval[k] = (bx2[k] > bx1[k]) && (by2[k] > by1[k]);
        bacc[k] = 0.0f;
    }

    const float4* imgrow = (const float4*)(img + (size_t)b * IMH * IMW);

    for (int r = 0; r < ROWS_PER_WARP; ++r) {
        const int row = rowBase + r;

        // 1) Coalesced global load, stage raw row into swizzled SMEM.
#pragma unroll
        for (int j = 0; j < 8; j++) {
            float4 v = imgrow[(size_t)row * (IMW / 4) + lane + 32 * j];
            *(float4*)(ep + swz(4 * lane + 128 * j)) = v;
        }
        __syncwarp();

        // 2) Pass 1: per-thread sum of its contiguous 32-element chunk.
        float tot = 0.0f;
#pragma unroll
        for (int j = 0; j < 8; j++) {
            float4 u = *(const float4*)(ep + swz(32 * lane + 4 * j));
            tot += (u.x + u.y) + (u.z + u.w);
        }

        // 3) Warp exclusive scan of chunk totals.
        float s = tot;
#pragma unroll
        for (int o = 1; o < 32; o <<= 1) {
            float u = __shfl_up_sync(0xffffffffu, s, o);
            if (lane >= o) s += u;
        }
        float run = s - tot;  // exclusive offset of this chunk

        // 4) Pass 2: rewrite chunk with exclusive prefixes.
#pragma unroll
        for (int j = 0; j < 8; j++) {
            float4 u = *(const float4*)(ep + swz(32 * lane + 4 * j));
            float4 o4;
            o4.x = run; run += u.x;
            o4.y = run; run += u.y;
            o4.z = run; run += u.z;
            o4.w = run; run += u.w;
            *(float4*)(ep + swz(32 * lane + 4 * j)) = o4;
        }
        if (lane == 31) ep[1024] = run;  // epref[1024] = row total (swz(1024)==1024)
        __syncwarp();

        // 5) Serve this row's contribution for all 96 boxes (3 per lane).
#pragma unroll
        for (int k = 0; k < 3; k++) {
            if (bval[k] && by1[k] <= row && row < by2[k])
                bacc[k] += ep[swz(bx2[k])] - ep[swz(bx1[k])];
        }
        __syncwarp();  // protect ep before next row overwrites
    }

#pragma unroll
    for (int k = 0; k < 3; k++)
        if (bval[k] && bacc[k] != 0.0f)
            atomicAdd(&g_boxsum[b * NBOX + lane + 32 * k], bacc[k]);

    // ---- last-block finalization: loss + state reset (fused epilogue) ----
    __shared__ unsigned lastflag;
    __threadfence();
    if (t == 0) {
        unsigned v = atomicAdd(&g_done, 1u);
        lastflag = (v == (unsigned)(gridDim.x - 1));
    }
    __syncthreads();

    if (lastflag) {
        float sum = 0.0f;
        for (int i = t; i < BATCH * NBOX; i += NTHREADS) {
            float sv = __ldcg(&g_boxsum[i]);  // L1-bypass: see other blocks' atomics
            g_boxsum[i] = 0.0f;               // reset for next replay
            float d = 1.0f - sv;              // invalid boxes stayed 0 -> contribute 1
            sum += (d > 0.0f) ? d : 0.0f;
        }
        __shared__ float red[WARPS];
#pragma unroll
        for (int o = 16; o; o >>= 1) sum += __shfl_down_sync(0xffffffffu, sum, o);
        if (lane == 0) red[w] = sum;
        __syncthreads();
        if (w == 0) {
            sum = (lane < WARPS) ? red[lane] : 0.0f;
#pragma unroll
            for (int o = 16; o; o >>= 1) sum += __shfl_down_sync(0xffffffffu, sum, o);
            if (lane == 0) {
                *out = sum;
                g_done = 0u;  // reset counter for next replay
            }
        }
    }
}

extern "C" void kernel_launch(void* const* d_in, const int* in_sizes, int n_in,
                              void* d_out, int out_size) {
    const float* img = (const float*)d_in[0];  // (32,1,1024,1024) fp32
    const int*   bb  = (const int*)d_in[1];    // (32,96,4) int32
    float* out = (float*)d_out;

    fused_kernel<<<GRID, NTHREADS>>>(img, bb, out);
}